// round 1
// baseline (speedup 1.0000x reference)
#include <cuda_runtime.h>
#include <math.h>

// ---------------- problem constants ----------------
#define BATCH   4096
#define C1      64
#define IMH     28
#define IMW     28
#define OH      24      // conv out
#define PH      12      // pooled
#define POS     (PH*PH)         // 144
#define CL      (C1*POS)        // 9216
#define NFC     1024
#define K1K     400
#define KFC     100
#define NCLS    10
#define CAP     512             // sparse list capacity per row

// ---------------- scratch (static device globals; no allocation) ----------------
__device__ __align__(16) float          g_Wt[CL * NFC];      // masked fc1_w, transposed [j][n]  (37.7 MB)
__device__ float          g_val[BATCH * CAP];
__device__ unsigned short g_idx[BATCH * CAP];
__device__ int            g_cnt[BATCH];

// order-preserving float -> uint transform
__device__ __forceinline__ unsigned int f2u(float f) {
    unsigned int u = __float_as_uint(f);
    return (u & 0x80000000u) ? ~u : (u | 0x80000000u);
}

// ================= K0: mask + transpose fc1 weights =================
__global__ void k_prep(const float* __restrict__ w, const float* __restrict__ m) {
    __shared__ float tile[32][33];
    int jb = blockIdx.x * 32;     // 288 tiles along j (9216)
    int nb = blockIdx.y * 32;     // 32 tiles along n (1024)
    int tx = threadIdx.x, ty = threadIdx.y;   // (32, 8)
#pragma unroll
    for (int r = 0; r < 32; r += 8) {
        int n = nb + ty + r;
        int j = jb + tx;
        float wv = w[n * CL + j];
        float mv = m[n * CL + j];
        tile[ty + r][tx] = (mv < 0.5f) ? wv : 0.0f;
    }
    __syncthreads();
#pragma unroll
    for (int r = 0; r < 32; r += 8) {
        int j = jb + ty + r;
        int n = nb + tx;
        g_Wt[j * NFC + n] = tile[tx][ty + r];
    }
}

// ================= K1: fused conv + pool + kwinners(400/9216) =================
#define T1 288   // 2 channel-groups x 144 positions; 9 warps

__global__ void __launch_bounds__(T1) k_conv_pool_kw(
    const float* __restrict__ x, const float* __restrict__ cw,
    const float* __restrict__ cb, const float* __restrict__ duty)
{
    __shared__ float img[IMH * IMW];       // 784
    __shared__ float wts[C1 * 25];         // 1600
    __shared__ float bias[C1];
    __shared__ float boost[C1];
    __shared__ float pooled[CL];           // 9216 (36 KB)
    __shared__ unsigned int hist[256];
    __shared__ int s_wsum[16];
    __shared__ unsigned int sel_prefix;
    __shared__ int sel_kr;
    __shared__ int sel_total;

    const int tid = threadIdx.x;
    const int b   = blockIdx.x;

    const float* xb = x + b * (IMH * IMW);
    for (int i = tid; i < IMH * IMW; i += T1) img[i] = xb[i];
    for (int i = tid; i < C1 * 25;   i += T1) wts[i] = cw[i];
    if (tid < C1) {
        bias[tid]  = cb[tid];
        boost[tid] = expf(400.0f / 9216.0f - duty[tid]);   // boostStrength = 1
    }
    __syncthreads();

    // ---- conv 5x5 + maxpool 2x2, channel-inner loop, patch in registers ----
    {
        int pos = tid % POS;          // 0..143
        int cg  = tid / POS;          // 0..1
        int py = pos / PH, px = pos % PH;
        int r0 = py * 2, c0 = px * 2;
        float p[36];
#pragma unroll
        for (int u = 0; u < 6; u++)
#pragma unroll
            for (int v = 0; v < 6; v++)
                p[u * 6 + v] = img[(r0 + u) * IMW + (c0 + v)];
        int cbase = cg * 32;
        for (int cc = 0; cc < 32; cc++) {
            int c = cbase + cc;
            const float* wc = wts + c * 25;
            float s00 = 0.f, s01 = 0.f, s10 = 0.f, s11 = 0.f;
#pragma unroll
            for (int u = 0; u < 5; u++) {
#pragma unroll
                for (int v = 0; v < 5; v++) {
                    float wv = wc[u * 5 + v];
                    s00 = fmaf(p[u * 6 + v],     wv, s00);
                    s01 = fmaf(p[u * 6 + v + 1], wv, s01);
                    s10 = fmaf(p[u * 6 + 6 + v], wv, s10);
                    s11 = fmaf(p[u * 6 + 7 + v], wv, s11);
                }
            }
            pooled[c * POS + pos] =
                fmaxf(fmaxf(s00, s01), fmaxf(s10, s11)) + bias[c];
        }
    }
    __syncthreads();

    // ---- exact k-th largest of boosted values via 4-pass radix select ----
    if (tid == 0) { sel_prefix = 0u; sel_kr = K1K; }
    __syncthreads();
    for (int shift = 24; shift >= 0; shift -= 8) {
        if (tid < 256) hist[tid] = 0u;
        __syncthreads();
        unsigned int pfx    = sel_prefix;
        unsigned int himask = (shift == 24) ? 0u : (0xFFFFFFFFu << (shift + 8));
        for (int i = tid; i < CL; i += T1) {
            unsigned int u = f2u(pooled[i] * boost[i / POS]);
            if ((u & himask) == pfx) atomicAdd(&hist[(u >> shift) & 255], 1u);
        }
        __syncthreads();
        if (tid == 0) {
            int kk = sel_kr; unsigned int acc = 0;
            for (int bin = 255; bin >= 0; --bin) {
                unsigned int h = hist[bin];
                if (acc + h >= (unsigned)kk) {
                    sel_prefix = pfx | ((unsigned)bin << shift);
                    sel_kr = kk - (int)acc;
                    break;
                }
                acc += h;
            }
        }
        __syncthreads();
    }
    unsigned int thr = sel_prefix;

    // ---- deterministic compaction (count -> shfl scan -> write) ----
    int mycnt = 0;
    for (int i = tid; i < CL; i += T1)
        if (f2u(pooled[i] * boost[i / POS]) >= thr) mycnt++;

    int lane = tid & 31, wrp = tid >> 5;
    int v = mycnt;
#pragma unroll
    for (int d = 1; d < 32; d <<= 1) {
        int t = __shfl_up_sync(0xFFFFFFFFu, v, d);
        if (lane >= d) v += t;
    }
    if (lane == 31) s_wsum[wrp] = v;
    __syncthreads();
    if (tid == 0) {
        int a = 0;
        for (int w = 0; w < T1 / 32; w++) { int t = s_wsum[w]; s_wsum[w] = a; a += t; }
        sel_total = a;
    }
    __syncthreads();
    int off = s_wsum[wrp] + v - mycnt;   // exclusive offset, fixed (deterministic) order
    for (int i = tid; i < CL; i += T1) {
        if (f2u(pooled[i] * boost[i / POS]) >= thr) {
            if (off < CAP) {
                g_idx[b * CAP + off] = (unsigned short)i;
                g_val[b * CAP + off] = pooled[i];
            }
            off++;
        }
    }
    if (tid == 0) g_cnt[b] = sel_total > CAP ? CAP : sel_total;
}

// ================= K2: sparse fc1 + kwinners(100/1024) + fc2 + log_softmax =================
#define T2 256

__global__ void __launch_bounds__(T2) k_fc_out(
    const float* __restrict__ fc1_b, const float* __restrict__ duty_fc,
    const float* __restrict__ w2,    const float* __restrict__ b2,
    float* __restrict__ out)
{
    __shared__ float         s_val[CAP];
    __shared__ int           s_idx[CAP];
    __shared__ float         s_h[NFC];
    __shared__ unsigned int  s_keys[NFC];
    __shared__ unsigned int  hist[256];
    __shared__ unsigned int  sel_prefix;
    __shared__ int           sel_kr;
    __shared__ float         s_red[8][10];
    __shared__ float         s_logits[10];
    __shared__ float         s_lse;

    const int tid = threadIdx.x;
    const int b   = blockIdx.x;

    int cnt = g_cnt[b];
    for (int i = tid; i < cnt; i += T2) {
        s_idx[i] = g_idx[b * CAP + i];
        s_val[i] = g_val[b * CAP + i];
    }
    __syncthreads();

    // sparse accumulate: each thread owns 4 output neurons
    float a0 = 0.f, a1 = 0.f, a2 = 0.f, a3 = 0.f;
    const float4* __restrict__ W4 = (const float4*)g_Wt;
#pragma unroll 4
    for (int e = 0; e < cnt; e++) {
        float vv = s_val[e];
        int   j  = s_idx[e];
        float4 w = W4[j * (NFC / 4) + tid];
        a0 = fmaf(vv, w.x, a0);
        a1 = fmaf(vv, w.y, a1);
        a2 = fmaf(vv, w.z, a2);
        a3 = fmaf(vv, w.w, a3);
    }

    const float kdn = 100.0f / 1024.0f;
    {
        int n = tid * 4;
        float h0 = a0 + fc1_b[n],     h1 = a1 + fc1_b[n + 1];
        float h2 = a2 + fc1_b[n + 2], h3 = a3 + fc1_b[n + 3];
        s_h[n] = h0; s_h[n + 1] = h1; s_h[n + 2] = h2; s_h[n + 3] = h3;
        s_keys[n]     = f2u(h0 * expf(kdn - duty_fc[n]));
        s_keys[n + 1] = f2u(h1 * expf(kdn - duty_fc[n + 1]));
        s_keys[n + 2] = f2u(h2 * expf(kdn - duty_fc[n + 2]));
        s_keys[n + 3] = f2u(h3 * expf(kdn - duty_fc[n + 3]));
    }
    __syncthreads();

    // radix select: exact 100th largest boosted h
    if (tid == 0) { sel_prefix = 0u; sel_kr = KFC; }
    __syncthreads();
    for (int shift = 24; shift >= 0; shift -= 8) {
        hist[tid] = 0u;
        __syncthreads();
        unsigned int pfx    = sel_prefix;
        unsigned int himask = (shift == 24) ? 0u : (0xFFFFFFFFu << (shift + 8));
#pragma unroll
        for (int q = 0; q < 4; q++) {
            unsigned int u = s_keys[tid * 4 + q];
            if ((u & himask) == pfx) atomicAdd(&hist[(u >> shift) & 255], 1u);
        }
        __syncthreads();
        if (tid == 0) {
            int kk = sel_kr; unsigned int acc = 0;
            for (int bin = 255; bin >= 0; --bin) {
                unsigned int h = hist[bin];
                if (acc + h >= (unsigned)kk) {
                    sel_prefix = pfx | ((unsigned)bin << shift);
                    sel_kr = kk - (int)acc;
                    break;
                }
                acc += h;
            }
        }
        __syncthreads();
    }
    unsigned int thr = sel_prefix;

    // fc2 over winners
    float part[10];
#pragma unroll
    for (int c = 0; c < 10; c++) part[c] = 0.f;
#pragma unroll
    for (int q = 0; q < 4; q++) {
        int n = tid * 4 + q;
        if (s_keys[n] >= thr) {
            float hv = s_h[n];
#pragma unroll
            for (int c = 0; c < 10; c++)
                part[c] = fmaf(hv, w2[c * NFC + n], part[c]);
        }
    }
    int lane = tid & 31, wrp = tid >> 5;
#pragma unroll
    for (int c = 0; c < 10; c++) {
        float pv = part[c];
#pragma unroll
        for (int d = 16; d > 0; d >>= 1)
            pv += __shfl_down_sync(0xFFFFFFFFu, pv, d);
        if (lane == 0) s_red[wrp][c] = pv;
    }
    __syncthreads();
    if (tid < 10) {
        float s = 0.f;
#pragma unroll
        for (int w = 0; w < 8; w++) s += s_red[w][tid];
        s_logits[tid] = s + b2[tid];
    }
    __syncthreads();
    if (tid == 0) {
        float mx = s_logits[0];
        for (int c = 1; c < 10; c++) mx = fmaxf(mx, s_logits[c]);
        float se = 0.f;
        for (int c = 0; c < 10; c++) se += expf(s_logits[c] - mx);
        s_lse = mx + logf(se);
    }
    __syncthreads();
    if (tid < 10) out[b * 10 + tid] = s_logits[tid] - s_lse;
}

// ================= launch =================
extern "C" void kernel_launch(void* const* d_in, const int* in_sizes, int n_in,
                              void* d_out, int out_size)
{
    const float* x        = (const float*)d_in[0];   // [4096,1,28,28]
    const float* c1_w     = (const float*)d_in[1];   // [64,1,5,5]
    const float* c1_b     = (const float*)d_in[2];   // [64]
    const float* duty_cnn = (const float*)d_in[3];   // [1,64,1,1]
    const float* fc1_w    = (const float*)d_in[4];   // [1024,9216]
    const float* fc1_mask = (const float*)d_in[5];   // [1024,9216]
    const float* fc1_b    = (const float*)d_in[6];   // [1024]
    const float* duty_fc  = (const float*)d_in[7];   // [1024]
    const float* fc2_w    = (const float*)d_in[8];   // [10,1024]
    const float* fc2_b    = (const float*)d_in[9];   // [10]
    float* out = (float*)d_out;

    k_prep<<<dim3(CL / 32, NFC / 32), dim3(32, 8)>>>(fc1_w, fc1_mask);
    k_conv_pool_kw<<<BATCH, T1>>>(x, c1_w, c1_b, duty_cnn);
    k_fc_out<<<BATCH, T2>>>(fc1_b, duty_fc, fc2_w, fc2_b, out);
}